// round 5
// baseline (speedup 1.0000x reference)
#include <cuda_runtime.h>
#include <cuda_bf16.h>
#include <cstdint>

#define N1 262144
#define N2 65536
#define N3 16384
#define E1 524288
#define E2 262144
#define HD 256
#define HID 64
#define HEADS 4
#define OUTD 64
#define IND 128
#define NEG_SLOPE 0.2f

// ---------------- device scratch ----------------
__device__ float g_as1[(size_t)N1 * HEADS];
__device__ float g_ad1[(size_t)N2 * HEADS];
__device__ int   g_off1[N2 + 1];
__device__ int   g_cur1[N2];
__device__ int   g_srcs1[E1];
__device__ float g_alpha1[(size_t)E1 * HEADS];
__device__ float g_xagg[(size_t)N2 * HEADS * IND];
__device__ float g_hbn[(size_t)N2 * HD];
__device__ float g_h2[(size_t)N2 * OUTD];
__device__ float g_as2[N2];
__device__ float g_ad2[N3];
__device__ int   g_off2[N3 + 1];
__device__ int   g_cur2[N3];
__device__ int   g_srcs2[E2];
__device__ float g_alpha2[E2];
__device__ int   g_bsum[64];

__device__ float g_v1s[IND * HEADS];
__device__ float g_v1d[IND * HEADS];
__device__ float g_v2s[HD];
__device__ float g_v2d[HD];
__device__ float g_bnscale[HD];
__device__ float g_bnshift[HD];

// ---------------- fold ----------------
__global__ void fold_kernel(const float* __restrict__ W1s, const float* __restrict__ a1s,
                            const float* __restrict__ W1d, const float* __restrict__ a1d,
                            const float* __restrict__ W2s, const float* __restrict__ W2d,
                            const float* __restrict__ a2s, const float* __restrict__ a2d,
                            const float* __restrict__ b1, const float* __restrict__ gamma,
                            const float* __restrict__ beta, const float* __restrict__ mean,
                            const float* __restrict__ var) {
    int t = threadIdx.x;  // 512
    {
        int k = t >> 2, h = t & 3;
        float s1 = 0.f, d1 = 0.f;
        for (int c = 0; c < HID; c++) {
            s1 += W1s[k * HD + h * HID + c] * a1s[h * HID + c];
            d1 += W1d[k * HD + h * HID + c] * a1d[h * HID + c];
        }
        g_v1s[t] = s1;
        g_v1d[t] = d1;
    }
    if (t < HD) {
        float s2 = 0.f, d2 = 0.f;
        for (int c = 0; c < OUTD; c++) {
            s2 += W2s[t * OUTD + c] * a2s[c];
            d2 += W2d[t * OUTD + c] * a2d[c];
        }
        g_v2s[t] = s2;
        g_v2d[t] = d2;
        float sc = gamma[t] * rsqrtf(var[t] + 1e-5f);
        g_bnscale[t] = sc;
        g_bnshift[t] = beta[t] + (b1[t] - mean[t]) * sc;
    }
}

// ---------------- a_src1/a_dst1 ----------------
__global__ __launch_bounds__(256) void asrc1_kernel(const float* __restrict__ x) {
    __shared__ float sv1s[IND * HEADS], sv1d[IND * HEADS];
    int tid = threadIdx.x;
    for (int i = tid; i < IND * HEADS; i += 256) {
        sv1s[i] = g_v1s[i];
        sv1d[i] = g_v1d[i];
    }
    __syncthreads();
    int gw = (blockIdx.x * 256 + tid) >> 5;
    int lane = tid & 31;
    if (gw >= N1) return;
    float4 xv = *(const float4*)(x + (size_t)gw * IND + lane * 4);
    float xr[4] = {xv.x, xv.y, xv.z, xv.w};
    bool need_d = gw < N2;
    float s[4] = {0, 0, 0, 0}, dd[4] = {0, 0, 0, 0};
#pragma unroll
    for (int i = 0; i < 4; i++) {
        int k = lane * 4 + i;
#pragma unroll
        for (int h = 0; h < 4; h++) {
            s[h] += xr[i] * sv1s[k * HEADS + h];
            dd[h] += xr[i] * sv1d[k * HEADS + h];
        }
    }
#pragma unroll
    for (int off = 16; off > 0; off >>= 1)
#pragma unroll
        for (int h = 0; h < 4; h++) {
            s[h] += __shfl_down_sync(0xffffffffu, s[h], off);
            dd[h] += __shfl_down_sync(0xffffffffu, dd[h], off);
        }
    if (lane == 0) {
        *(float4*)(g_as1 + (size_t)gw * HEADS) = make_float4(s[0], s[1], s[2], s[3]);
        if (need_d)
            *(float4*)(g_ad1 + (size_t)gw * HEADS) = make_float4(dd[0], dd[1], dd[2], dd[3]);
    }
}

// ---------------- CSR build ----------------
__global__ void deg_kernel(const int* __restrict__ dst, int* __restrict__ cur, int n) {
    int i = blockIdx.x * blockDim.x + threadIdx.x;
    if (i < n) atomicAdd(&cur[dst[i]], 1);
}

// phase 1: block of 1024 threads scans 4096 elements
__global__ __launch_bounds__(1024) void scan_local(const int* __restrict__ cnt,
                                                   int* __restrict__ off,
                                                   int* __restrict__ bsum) {
    __shared__ int sm[1024];
    int t = threadIdx.x;
    int base = blockIdx.x * 4096 + t * 4;
    int4 v = *(const int4*)(cnt + base);
    int s = v.x + v.y + v.z + v.w;
    sm[t] = s;
    __syncthreads();
    for (int d = 1; d < 1024; d <<= 1) {
        int u = (t >= d) ? sm[t - d] : 0;
        __syncthreads();
        sm[t] += u;
        __syncthreads();
    }
    int excl = sm[t] - s;
    int4 o;
    o.x = excl;
    o.y = excl + v.x;
    o.z = o.y + v.y;
    o.w = o.z + v.z;
    *(int4*)(off + base) = o;
    if (t == 1023) bsum[blockIdx.x] = sm[1023];
}

// phase 2: scan of block sums (nb <= 32), writes total to off[n]
__global__ void scan_bsum(int* __restrict__ bsum, int* __restrict__ off, int nb, int n) {
    int t = threadIdx.x;  // 32 threads
    int orig = (t < nb) ? bsum[t] : 0;
    int v = orig;
    for (int d = 1; d < 32; d <<= 1) {
        int u = __shfl_up_sync(0xffffffffu, v, d);
        if (t >= d) v += u;
    }
    if (t < nb) bsum[t] = v - orig;
    if (t == 31) off[n] = v;
}

// phase 3: add block offsets, copy to cursor
__global__ __launch_bounds__(1024) void scan_add(int* __restrict__ off, int* __restrict__ cnt,
                                                 const int* __restrict__ bsum) {
    int i = blockIdx.x * 1024 + threadIdx.x;
    int v = off[i] + bsum[i >> 12];
    off[i] = v;
    cnt[i] = v;
}

__global__ void fill_kernel(const int* __restrict__ src, const int* __restrict__ dst,
                            int* __restrict__ cur, int* __restrict__ srcs, int n) {
    int i = blockIdx.x * blockDim.x + threadIdx.x;
    if (i >= n) return;
    int pos = atomicAdd(&cur[dst[i]], 1);
    srcs[pos] = src[i];
}

// ---------------- layer1 fused softmax + aggregation: warp per dst ----------------
__global__ __launch_bounds__(256) void l1_edge_kernel(const float* __restrict__ x) {
    int d = (blockIdx.x * blockDim.x + threadIdx.x) >> 5;
    int lane = threadIdx.x & 31;
    if (d >= N2) return;
    int beg = g_off1[d], end = g_off1[d + 1];
    float4 adv = *(const float4*)(g_ad1 + (size_t)d * HEADS);
    float ad[4] = {adv.x, adv.y, adv.z, adv.w};
    float den[4] = {0, 0, 0, 0};
    for (int e = beg + lane; e < end; e += 32) {
        int s = g_srcs1[e];
        float4 asv = *(const float4*)(g_as1 + (size_t)s * HEADS);
        float as[4] = {asv.x, asv.y, asv.z, asv.w};
        float p[4];
#pragma unroll
        for (int h = 0; h < 4; h++) {
            float ee = as[h] + ad[h];
            ee = ee > 0.f ? ee : NEG_SLOPE * ee;
            p[h] = expf(ee);
            den[h] += p[h];
        }
        *(float4*)(g_alpha1 + (size_t)e * HEADS) = make_float4(p[0], p[1], p[2], p[3]);
    }
#pragma unroll
    for (int off = 16; off > 0; off >>= 1)
#pragma unroll
        for (int h = 0; h < 4; h++) den[h] += __shfl_xor_sync(0xffffffffu, den[h], off);
    float rd[4];
#pragma unroll
    for (int h = 0; h < 4; h++) rd[h] = 1.f / fmaxf(den[h], 1e-16f);
    __syncwarp();
    float acc[4][4];
#pragma unroll
    for (int h = 0; h < 4; h++)
#pragma unroll
        for (int j = 0; j < 4; j++) acc[h][j] = 0.f;
    for (int e = beg; e < end; e++) {
        int s = g_srcs1[e];
        float4 al = *(const float4*)(g_alpha1 + (size_t)e * HEADS);
        float4 xv = *(const float4*)(x + (size_t)s * IND + lane * 4);
        float a[4] = {al.x * rd[0], al.y * rd[1], al.z * rd[2], al.w * rd[3]};
        float xr[4] = {xv.x, xv.y, xv.z, xv.w};
#pragma unroll
        for (int h = 0; h < 4; h++)
#pragma unroll
            for (int j = 0; j < 4; j++) acc[h][j] += a[h] * xr[j];
    }
#pragma unroll
    for (int h = 0; h < 4; h++)
        *(float4*)(g_xagg + ((size_t)d * HEADS + h) * IND + lane * 4) =
            make_float4(acc[h][0], acc[h][1], acc[h][2], acc[h][3]);
}

// ---------------- GEMM-L1: hbn = elu(bn(xagg @ W1s_head)) + a2 partial dots ----------------
// 256 threads, tile 256 rows x 64 cols (one head), thread = 8x8, K=128 in chunks of 64
#define GL1_SMEM ((64 * 64 + 64 * 260) * 4)
__global__ __launch_bounds__(256) void gemm_l1_kernel(const float* __restrict__ W1s) {
    extern __shared__ float sm[];
    float* ws = sm;             // 64 k x 64 c
    float* xs = sm + 64 * 64;   // xs[k*260 + r]
    int tid = threadIdx.x;
    int h = blockIdx.y;
    int row0 = blockIdx.x * 256;
    int tc = tid & 7, tr = tid >> 3;
    float acc[8][8];
#pragma unroll
    for (int a = 0; a < 8; a++)
#pragma unroll
        for (int b = 0; b < 8; b++) acc[a][b] = 0.f;

    for (int kb = 0; kb < IND; kb += 64) {
        __syncthreads();
        for (int i = tid; i < 64 * 64; i += 256) {
            int k = i >> 6, c = i & 63;
            ws[i] = W1s[(kb + k) * HD + h * HID + c];
        }
        for (int i = tid; i < 64 * 256; i += 256) {
            int r = i >> 6, k = i & 63;
            xs[k * 260 + r] = g_xagg[((size_t)(row0 + r) * HEADS + h) * IND + kb + k];
        }
        __syncthreads();
#pragma unroll 2
        for (int k = 0; k < 64; k++) {
            float4 x0 = *(const float4*)(xs + k * 260 + tr * 8);
            float4 x1 = *(const float4*)(xs + k * 260 + tr * 8 + 4);
            float4 w0 = *(const float4*)(ws + k * 64 + tc * 8);
            float4 w1 = *(const float4*)(ws + k * 64 + tc * 8 + 4);
            float xr[8] = {x0.x, x0.y, x0.z, x0.w, x1.x, x1.y, x1.z, x1.w};
            float wv[8] = {w0.x, w0.y, w0.z, w0.w, w1.x, w1.y, w1.z, w1.w};
#pragma unroll
            for (int a = 0; a < 8; a++)
#pragma unroll
                for (int b = 0; b < 8; b++) acc[a][b] += xr[a] * wv[b];
        }
    }

    float sc[8], sh[8], v2s[8], v2d[8];
#pragma unroll
    for (int b = 0; b < 8; b++) {
        int col = h * HID + tc * 8 + b;
        sc[b] = g_bnscale[col];
        sh[b] = g_bnshift[col];
        v2s[b] = g_v2s[col];
        v2d[b] = g_v2d[col];
    }
#pragma unroll
    for (int a = 0; a < 8; a++) {
        int row = row0 + tr * 8 + a;
        float vo[8];
        float ps = 0.f, pd = 0.f;
#pragma unroll
        for (int b = 0; b < 8; b++) {
            float v = acc[a][b] * sc[b] + sh[b];
            v = v > 0.f ? v : expm1f(v);
            vo[b] = v;
            ps += v * v2s[b];
            pd += v * v2d[b];
        }
        float* o = g_hbn + (size_t)row * HD + h * HID + tc * 8;
        *(float4*)(o)     = make_float4(vo[0], vo[1], vo[2], vo[3]);
        *(float4*)(o + 4) = make_float4(vo[4], vo[5], vo[6], vo[7]);
        // reduce ps/pd across the 8 tc lanes (contiguous lanes within warp)
#pragma unroll
        for (int off = 4; off > 0; off >>= 1) {
            ps += __shfl_down_sync(0xffffffffu, ps, off, 8);
            pd += __shfl_down_sync(0xffffffffu, pd, off, 8);
        }
        if (tc == 0) {
            atomicAdd(&g_as2[row], ps);
            if (row < N3) atomicAdd(&g_ad2[row], pd);
        }
    }
}

// ---------------- GEMM-L2: h2 = hbn @ W2s ----------------
#define GL2_SMEM ((64 * 64 + 64 * 260) * 4)
__global__ __launch_bounds__(256) void gemm_l2_kernel(const float* __restrict__ W2s) {
    extern __shared__ float sm[];
    float* ws = sm;
    float* xs = sm + 64 * 64;
    int tid = threadIdx.x;
    int row0 = blockIdx.x * 256;
    int tc = tid & 7, tr = tid >> 3;
    float acc[8][8];
#pragma unroll
    for (int a = 0; a < 8; a++)
#pragma unroll
        for (int b = 0; b < 8; b++) acc[a][b] = 0.f;

    for (int kb = 0; kb < HD; kb += 64) {
        __syncthreads();
        for (int i = tid; i < 64 * 64; i += 256) {
            int k = i >> 6, c = i & 63;
            ws[i] = W2s[(kb + k) * OUTD + c];
        }
        for (int i = tid; i < 64 * 256; i += 256) {
            int r = i >> 6, k = i & 63;
            xs[k * 260 + r] = g_hbn[(size_t)(row0 + r) * HD + kb + k];
        }
        __syncthreads();
#pragma unroll 2
        for (int k = 0; k < 64; k++) {
            float4 x0 = *(const float4*)(xs + k * 260 + tr * 8);
            float4 x1 = *(const float4*)(xs + k * 260 + tr * 8 + 4);
            float4 w0 = *(const float4*)(ws + k * 64 + tc * 8);
            float4 w1 = *(const float4*)(ws + k * 64 + tc * 8 + 4);
            float xr[8] = {x0.x, x0.y, x0.z, x0.w, x1.x, x1.y, x1.z, x1.w};
            float wv[8] = {w0.x, w0.y, w0.z, w0.w, w1.x, w1.y, w1.z, w1.w};
#pragma unroll
            for (int a = 0; a < 8; a++)
#pragma unroll
                for (int b = 0; b < 8; b++) acc[a][b] += xr[a] * wv[b];
        }
    }
#pragma unroll
    for (int a = 0; a < 8; a++) {
        float* o = g_h2 + (size_t)(row0 + tr * 8 + a) * OUTD + tc * 8;
        *(float4*)(o)     = make_float4(acc[a][0], acc[a][1], acc[a][2], acc[a][3]);
        *(float4*)(o + 4) = make_float4(acc[a][4], acc[a][5], acc[a][6], acc[a][7]);
    }
}

// ---------------- layer2 fused softmax + aggregation into d_out ----------------
__global__ __launch_bounds__(256) void l2_edge_kernel(float* __restrict__ out,
                                                      const float* __restrict__ b2) {
    int d = (blockIdx.x * blockDim.x + threadIdx.x) >> 5;
    int lane = threadIdx.x & 31;
    if (d >= N3) return;
    int beg = g_off2[d], end = g_off2[d + 1];
    float ad = g_ad2[d];
    float den = 0.f;
    for (int e = beg + lane; e < end; e += 32) {
        int s = g_srcs2[e];
        float ee = g_as2[s] + ad;
        ee = ee > 0.f ? ee : NEG_SLOPE * ee;
        float p = expf(ee);
        g_alpha2[e] = p;
        den += p;
    }
#pragma unroll
    for (int off = 16; off > 0; off >>= 1) den += __shfl_xor_sync(0xffffffffu, den, off);
    float rd = 1.f / fmaxf(den, 1e-16f);
    __syncwarp();
    float ax = 0.f, ay = 0.f;
    for (int e = beg; e < end; e++) {
        int s = g_srcs2[e];
        float a = g_alpha2[e] * rd;
        float2 v = *(const float2*)(g_h2 + (size_t)s * OUTD + lane * 2);
        ax += a * v.x;
        ay += a * v.y;
    }
    out[(size_t)d * OUTD + lane * 2]     = ax + b2[lane * 2];
    out[(size_t)d * OUTD + lane * 2 + 1] = ay + b2[lane * 2 + 1];
}

// ---------------- launch ----------------
extern "C" void kernel_launch(void* const* d_in, const int* in_sizes, int n_in,
                              void* d_out, int out_size) {
    const float* x        = (const float*)d_in[0];
    const float* W1_src   = (const float*)d_in[1];
    const float* W1_dst   = (const float*)d_in[2];
    const float* att1_src = (const float*)d_in[3];
    const float* att1_dst = (const float*)d_in[4];
    const float* b1       = (const float*)d_in[5];
    const float* gamma    = (const float*)d_in[6];
    const float* beta     = (const float*)d_in[7];
    const float* run_mean = (const float*)d_in[8];
    const float* run_var  = (const float*)d_in[9];
    const float* W2_src   = (const float*)d_in[10];
    const float* W2_dst   = (const float*)d_in[11];
    const float* att2_src = (const float*)d_in[12];
    const float* att2_dst = (const float*)d_in[13];
    const float* b2       = (const float*)d_in[14];
    const int*   src1     = (const int*)d_in[15];
    const int*   dst1     = (const int*)d_in[16];
    const int*   src2     = (const int*)d_in[17];
    const int*   dst2     = (const int*)d_in[18];
    float* out = (float*)d_out;

    cudaFuncSetAttribute(gemm_l1_kernel, cudaFuncAttributeMaxDynamicSharedMemorySize, GL1_SMEM);
    cudaFuncSetAttribute(gemm_l2_kernel, cudaFuncAttributeMaxDynamicSharedMemorySize, GL2_SMEM);

    void* tmp;
    cudaGetSymbolAddress(&tmp, g_cur1);  int* d_cur1 = (int*)tmp;
    cudaGetSymbolAddress(&tmp, g_cur2);  int* d_cur2 = (int*)tmp;
    cudaGetSymbolAddress(&tmp, g_off1);  int* d_off1 = (int*)tmp;
    cudaGetSymbolAddress(&tmp, g_srcs1); int* d_srcs1 = (int*)tmp;
    cudaGetSymbolAddress(&tmp, g_off2);  int* d_off2 = (int*)tmp;
    cudaGetSymbolAddress(&tmp, g_srcs2); int* d_srcs2 = (int*)tmp;
    cudaGetSymbolAddress(&tmp, g_bsum);  int* d_bsum = (int*)tmp;
    cudaGetSymbolAddress(&tmp, g_as2);   float* d_as2 = (float*)tmp;
    cudaGetSymbolAddress(&tmp, g_ad2);   float* d_ad2 = (float*)tmp;

    cudaMemsetAsync(d_cur1, 0, N2 * sizeof(int), 0);
    cudaMemsetAsync(d_cur2, 0, N3 * sizeof(int), 0);
    cudaMemsetAsync(d_as2, 0, N2 * sizeof(float), 0);
    cudaMemsetAsync(d_ad2, 0, N3 * sizeof(float), 0);

    fold_kernel<<<1, 512>>>(W1_src, att1_src, W1_dst, att1_dst, W2_src, W2_dst,
                            att2_src, att2_dst, b1, gamma, beta, run_mean, run_var);

    asrc1_kernel<<<N1 * 32 / 256, 256>>>(x);

    // CSR layer1 (fast scan)
    deg_kernel<<<E1 / 256, 256>>>(dst1, d_cur1, E1);
    scan_local<<<N2 / 4096, 1024>>>(d_cur1, d_off1, d_bsum);
    scan_bsum<<<1, 32>>>(d_bsum, d_off1, N2 / 4096, N2);
    scan_add<<<N2 / 1024, 1024>>>(d_off1, d_cur1, d_bsum);
    fill_kernel<<<E1 / 256, 256>>>(src1, dst1, d_cur1, d_srcs1, E1);

    l1_edge_kernel<<<N2 / 8, 256>>>(x);

    gemm_l1_kernel<<<dim3(N2 / 256, HEADS), 256, GL1_SMEM>>>(W1_src);

    // CSR layer2
    deg_kernel<<<E2 / 256, 256>>>(dst2, d_cur2, E2);
    scan_local<<<N3 / 4096, 1024>>>(d_cur2, d_off2, d_bsum);
    scan_bsum<<<1, 32>>>(d_bsum, d_off2, N3 / 4096, N3);
    scan_add<<<N3 / 1024, 1024>>>(d_off2, d_cur2, d_bsum);
    fill_kernel<<<E2 / 256, 256>>>(src2, dst2, d_cur2, d_srcs2, E2);

    gemm_l2_kernel<<<N2 / 256, 256, GL2_SMEM>>>(W2_src);

    l2_edge_kernel<<<N3 / 8, 256>>>(out, b2);
}

// round 7
// speedup vs baseline: 1.6628x; 1.6628x over previous
#include <cuda_runtime.h>
#include <cuda_bf16.h>
#include <cstdint>

#define N1 262144
#define N2 65536
#define N3 16384
#define E1 524288
#define E2 262144
#define HD 256
#define HID 64
#define HEADS 4
#define OUTD 64
#define IND 128
#define NEG_SLOPE 0.2f

// ---------------- device scratch ----------------
__device__ float g_as1[(size_t)N1 * HEADS];
__device__ float g_ad1[(size_t)N2 * HEADS];
__device__ int   g_off1[N2 + 1];
__device__ int   g_cur1[N2];
__device__ int   g_srcs1[E1];
__device__ float g_alpha1[(size_t)E1 * HEADS];
__device__ float g_xagg[(size_t)N2 * HEADS * IND];
__device__ float g_hbn[(size_t)N2 * HD];
__device__ float g_h2[(size_t)N2 * OUTD];
__device__ float g_as2[N2];
__device__ float g_ad2[N3];
__device__ int   g_off2[N3 + 1];
__device__ int   g_cur2[N3];
__device__ int   g_srcs2[E2];
__device__ float g_alpha2[E2];
__device__ int   g_bsum[64];

__device__ float g_v1s[IND * HEADS];
__device__ float g_v1d[IND * HEADS];
__device__ float g_v2s[HD];
__device__ float g_v2d[HD];
__device__ float g_bnscale[HD];
__device__ float g_bnshift[HD];

// ---------------- mma.sync helper (HMMA on sm_103) ----------------
__device__ __forceinline__ void mma16816(float* d, uint32_t a0, uint32_t a1, uint32_t a2,
                                         uint32_t a3, uint32_t b0, uint32_t b1) {
    asm volatile(
        "mma.sync.aligned.m16n8k16.row.col.f32.bf16.bf16.f32 "
        "{%0,%1,%2,%3}, {%4,%5,%6,%7}, {%8,%9}, {%0,%1,%2,%3};"
        : "+f"(d[0]), "+f"(d[1]), "+f"(d[2]), "+f"(d[3])
        : "r"(a0), "r"(a1), "r"(a2), "r"(a3), "r"(b0), "r"(b1));
}

__device__ __forceinline__ void split_bf16(float v, unsigned short& hi, unsigned short& lo) {
    __nv_bfloat16 h = __float2bfloat16_rn(v);
    float r = v - __bfloat162float(h);
    __nv_bfloat16 l = __float2bfloat16_rn(r);
    hi = __bfloat16_as_ushort(h);
    lo = __bfloat16_as_ushort(l);
}
__device__ __forceinline__ uint32_t pack2(unsigned short a, unsigned short b) {
    return (uint32_t)a | ((uint32_t)b << 16);
}

// ---------------- fold ----------------
__global__ void fold_kernel(const float* __restrict__ W1s, const float* __restrict__ a1s,
                            const float* __restrict__ W1d, const float* __restrict__ a1d,
                            const float* __restrict__ W2s, const float* __restrict__ W2d,
                            const float* __restrict__ a2s, const float* __restrict__ a2d,
                            const float* __restrict__ b1, const float* __restrict__ gamma,
                            const float* __restrict__ beta, const float* __restrict__ mean,
                            const float* __restrict__ var) {
    int t = threadIdx.x;  // 512
    {
        int k = t >> 2, h = t & 3;
        float s1 = 0.f, d1 = 0.f;
        for (int c = 0; c < HID; c++) {
            s1 += W1s[k * HD + h * HID + c] * a1s[h * HID + c];
            d1 += W1d[k * HD + h * HID + c] * a1d[h * HID + c];
        }
        g_v1s[t] = s1;
        g_v1d[t] = d1;
    }
    if (t < HD) {
        float s2 = 0.f, d2 = 0.f;
        for (int c = 0; c < OUTD; c++) {
            s2 += W2s[t * OUTD + c] * a2s[c];
            d2 += W2d[t * OUTD + c] * a2d[c];
        }
        g_v2s[t] = s2;
        g_v2d[t] = d2;
        float sc = gamma[t] * rsqrtf(var[t] + 1e-5f);
        g_bnscale[t] = sc;
        g_bnshift[t] = beta[t] + (b1[t] - mean[t]) * sc;
    }
}

// ---------------- a_src1/a_dst1 ----------------
__global__ __launch_bounds__(256) void asrc1_kernel(const float* __restrict__ x) {
    __shared__ float sv1s[IND * HEADS], sv1d[IND * HEADS];
    int tid = threadIdx.x;
    for (int i = tid; i < IND * HEADS; i += 256) {
        sv1s[i] = g_v1s[i];
        sv1d[i] = g_v1d[i];
    }
    __syncthreads();
    int gw = (blockIdx.x * 256 + tid) >> 5;
    int lane = tid & 31;
    if (gw >= N1) return;
    float4 xv = *(const float4*)(x + (size_t)gw * IND + lane * 4);
    float xr[4] = {xv.x, xv.y, xv.z, xv.w};
    bool need_d = gw < N2;
    float s[4] = {0, 0, 0, 0}, dd[4] = {0, 0, 0, 0};
#pragma unroll
    for (int i = 0; i < 4; i++) {
        int k = lane * 4 + i;
#pragma unroll
        for (int h = 0; h < 4; h++) {
            s[h] += xr[i] * sv1s[k * HEADS + h];
            dd[h] += xr[i] * sv1d[k * HEADS + h];
        }
    }
#pragma unroll
    for (int off = 16; off > 0; off >>= 1)
#pragma unroll
        for (int h = 0; h < 4; h++) {
            s[h] += __shfl_down_sync(0xffffffffu, s[h], off);
            dd[h] += __shfl_down_sync(0xffffffffu, dd[h], off);
        }
    if (lane == 0) {
        *(float4*)(g_as1 + (size_t)gw * HEADS) = make_float4(s[0], s[1], s[2], s[3]);
        if (need_d)
            *(float4*)(g_ad1 + (size_t)gw * HEADS) = make_float4(dd[0], dd[1], dd[2], dd[3]);
    }
}

// ---------------- CSR build ----------------
__global__ void deg_kernel(const int* __restrict__ dst, int* __restrict__ cur, int n) {
    int i = blockIdx.x * blockDim.x + threadIdx.x;
    if (i < n) atomicAdd(&cur[dst[i]], 1);
}

__global__ __launch_bounds__(1024) void scan_local(const int* __restrict__ cnt,
                                                   int* __restrict__ off,
                                                   int* __restrict__ bsum) {
    __shared__ int sm[1024];
    int t = threadIdx.x;
    int base = blockIdx.x * 4096 + t * 4;
    int4 v = *(const int4*)(cnt + base);
    int s = v.x + v.y + v.z + v.w;
    sm[t] = s;
    __syncthreads();
    for (int d = 1; d < 1024; d <<= 1) {
        int u = (t >= d) ? sm[t - d] : 0;
        __syncthreads();
        sm[t] += u;
        __syncthreads();
    }
    int excl = sm[t] - s;
    int4 o;
    o.x = excl;
    o.y = excl + v.x;
    o.z = o.y + v.y;
    o.w = o.z + v.z;
    *(int4*)(off + base) = o;
    if (t == 1023) bsum[blockIdx.x] = sm[1023];
}

__global__ void scan_bsum(int* __restrict__ bsum, int* __restrict__ off, int nb, int n) {
    int t = threadIdx.x;
    int orig = (t < nb) ? bsum[t] : 0;
    int v = orig;
    for (int d = 1; d < 32; d <<= 1) {
        int u = __shfl_up_sync(0xffffffffu, v, d);
        if (t >= d) v += u;
    }
    if (t < nb) bsum[t] = v - orig;
    if (t == 31) off[n] = v;
}

__global__ __launch_bounds__(1024) void scan_add(int* __restrict__ off, int* __restrict__ cnt,
                                                 const int* __restrict__ bsum) {
    int i = blockIdx.x * 1024 + threadIdx.x;
    int v = off[i] + bsum[i >> 12];
    off[i] = v;
    cnt[i] = v;
}

__global__ void fill_kernel(const int* __restrict__ src, const int* __restrict__ dst,
                            int* __restrict__ cur, int* __restrict__ srcs, int n) {
    int i = blockIdx.x * blockDim.x + threadIdx.x;
    if (i >= n) return;
    int pos = atomicAdd(&cur[dst[i]], 1);
    srcs[pos] = src[i];
}

// ---------------- layer1 softmax alphas: warp per dst ----------------
__global__ void alpha1_kernel() {
    int d = (blockIdx.x * blockDim.x + threadIdx.x) >> 5;
    int lane = threadIdx.x & 31;
    if (d >= N2) return;
    int beg = g_off1[d], end = g_off1[d + 1];
    if (beg == end) return;
    float4 adv = *(const float4*)(g_ad1 + (size_t)d * HEADS);
    float ad[4] = {adv.x, adv.y, adv.z, adv.w};
    float den[4] = {0, 0, 0, 0};
    for (int e = beg + lane; e < end; e += 32) {
        int s = g_srcs1[e];
        float4 asv = *(const float4*)(g_as1 + (size_t)s * HEADS);
        float as[4] = {asv.x, asv.y, asv.z, asv.w};
        float p[4];
#pragma unroll
        for (int h = 0; h < 4; h++) {
            float ee = as[h] + ad[h];
            ee = ee > 0.f ? ee : NEG_SLOPE * ee;
            p[h] = expf(ee);
            den[h] += p[h];
        }
        *(float4*)(g_alpha1 + (size_t)e * HEADS) = make_float4(p[0], p[1], p[2], p[3]);
    }
#pragma unroll
    for (int off = 16; off > 0; off >>= 1)
#pragma unroll
        for (int h = 0; h < 4; h++) den[h] += __shfl_xor_sync(0xffffffffu, den[h], off);
    float rd[4];
#pragma unroll
    for (int h = 0; h < 4; h++) rd[h] = 1.f / fmaxf(den[h], 1e-16f);
    for (int e = beg + lane; e < end; e += 32) {
        float4 p = *(const float4*)(g_alpha1 + (size_t)e * HEADS);
        *(float4*)(g_alpha1 + (size_t)e * HEADS) =
            make_float4(p.x * rd[0], p.y * rd[1], p.z * rd[2], p.w * rd[3]);
    }
}

// ---------------- layer1 aggregation of x: warp per dst ----------------
__global__ void agg1_kernel(const float* __restrict__ x) {
    int d = (blockIdx.x * blockDim.x + threadIdx.x) >> 5;
    int lane = threadIdx.x & 31;
    if (d >= N2) return;
    int beg = g_off1[d], end = g_off1[d + 1];
    float acc[4][4];
#pragma unroll
    for (int h = 0; h < 4; h++)
#pragma unroll
        for (int j = 0; j < 4; j++) acc[h][j] = 0.f;
    for (int e = beg; e < end; e++) {
        int s = g_srcs1[e];
        float4 al = *(const float4*)(g_alpha1 + (size_t)e * HEADS);
        float4 xv = *(const float4*)(x + (size_t)s * IND + lane * 4);
        float a[4] = {al.x, al.y, al.z, al.w};
        float xr[4] = {xv.x, xv.y, xv.z, xv.w};
#pragma unroll
        for (int h = 0; h < 4; h++)
#pragma unroll
            for (int j = 0; j < 4; j++) acc[h][j] += a[h] * xr[j];
    }
#pragma unroll
    for (int h = 0; h < 4; h++)
        *(float4*)(g_xagg + ((size_t)d * HEADS + h) * IND + lane * 4) =
            make_float4(acc[h][0], acc[h][1], acc[h][2], acc[h][3]);
}

// ---------------- GEMM-L1 (mma.sync): hbn = elu(bn(xagg @ W1s_h)) ----------------
// grid (N2/128, HEADS), 256 threads (8 warps). M=128, N=64, K=128, split-bf16 x3.
// smem bf16 elems: AH[128*132] AL[...] BH[64*132] BL[...]; then cons floats.
#define SA 132
#define AH_OFF 0
#define AL_OFF (128 * SA)
#define BH_OFF (2 * 128 * SA)
#define BL_OFF (2 * 128 * SA + 64 * SA)
#define BF16_ELEMS (2 * 128 * SA + 2 * 64 * SA)
#define L1_SMEM (BF16_ELEMS * 2 + 128 * 4)
__global__ __launch_bounds__(256) void gemm_l1_mma(const float* __restrict__ W1s) {
    extern __shared__ __nv_bfloat16 smb[];
    unsigned short* sm = (unsigned short*)smb;
    float* cons = (float*)(sm + BF16_ELEMS);  // sc[64], sh[64]
    int tid = threadIdx.x;
    int h = blockIdx.y;
    int row0 = blockIdx.x * 128;

    if (tid < 64) {
        int col = h * HID + tid;
        cons[tid] = g_bnscale[col];
        cons[64 + tid] = g_bnshift[col];
    }
    // A tile: 128 x 128 from g_xagg
    for (int i = tid; i < 128 * 32; i += 256) {
        int row = i >> 5, k = (i & 31) * 4;
        float4 v = *(const float4*)(g_xagg + ((size_t)(row0 + row) * HEADS + h) * IND + k);
        unsigned short hi[4], lo[4];
        split_bf16(v.x, hi[0], lo[0]);
        split_bf16(v.y, hi[1], lo[1]);
        split_bf16(v.z, hi[2], lo[2]);
        split_bf16(v.w, hi[3], lo[3]);
        int o = row * SA + k;
        *(uint2*)(sm + AH_OFF + o) = make_uint2(pack2(hi[0], hi[1]), pack2(hi[2], hi[3]));
        *(uint2*)(sm + AL_OFF + o) = make_uint2(pack2(lo[0], lo[1]), pack2(lo[2], lo[3]));
    }
    // B tile: Bsm[n][k] = W1s[k][h*64+n]
    for (int i = tid; i < 64 * 128; i += 256) {
        int n = i & 63, k = i >> 6;
        float v = W1s[k * HD + h * HID + n];
        unsigned short hi, lo;
        split_bf16(v, hi, lo);
        sm[BH_OFF + n * SA + k] = hi;
        sm[BL_OFF + n * SA + k] = lo;
    }
    __syncthreads();

    int wid = tid >> 5, lane = tid & 31;
    int gr = lane >> 2, tg = lane & 3;
    int r0 = wid * 16;
    float acc[8][4];
#pragma unroll
    for (int nt = 0; nt < 8; nt++)
#pragma unroll
        for (int j = 0; j < 4; j++) acc[nt][j] = 0.f;

#pragma unroll
    for (int ks = 0; ks < 8; ks++) {
        int k0 = ks * 16;
        int abase = (r0 + gr) * SA + k0 + tg * 2;
        uint32_t ah0 = *(const uint32_t*)(sm + AH_OFF + abase);
        uint32_t ah1 = *(const uint32_t*)(sm + AH_OFF + abase + 8 * SA);
        uint32_t ah2 = *(const uint32_t*)(sm + AH_OFF + abase + 8);
        uint32_t ah3 = *(const uint32_t*)(sm + AH_OFF + abase + 8 * SA + 8);
        uint32_t al0 = *(const uint32_t*)(sm + AL_OFF + abase);
        uint32_t al1 = *(const uint32_t*)(sm + AL_OFF + abase + 8 * SA);
        uint32_t al2 = *(const uint32_t*)(sm + AL_OFF + abase + 8);
        uint32_t al3 = *(const uint32_t*)(sm + AL_OFF + abase + 8 * SA + 8);
#pragma unroll
        for (int nt = 0; nt < 8; nt++) {
            int bbase = (nt * 8 + gr) * SA + k0 + tg * 2;
            uint32_t bh0 = *(const uint32_t*)(sm + BH_OFF + bbase);
            uint32_t bh1 = *(const uint32_t*)(sm + BH_OFF + bbase + 8);
            uint32_t bl0 = *(const uint32_t*)(sm + BL_OFF + bbase);
            uint32_t bl1 = *(const uint32_t*)(sm + BL_OFF + bbase + 8);
            mma16816(acc[nt], ah0, ah1, ah2, ah3, bh0, bh1);
            mma16816(acc[nt], ah0, ah1, ah2, ah3, bl0, bl1);
            mma16816(acc[nt], al0, al1, al2, al3, bh0, bh1);
        }
    }

    int r1 = row0 + r0 + gr;
    int r2 = r1 + 8;
#pragma unroll
    for (int nt = 0; nt < 8; nt++) {
        int n = nt * 8 + tg * 2;
        float sc0 = cons[n], sc1 = cons[n + 1], sh0 = cons[64 + n], sh1 = cons[64 + n + 1];
        float v0 = acc[nt][0] * sc0 + sh0;
        float v1 = acc[nt][1] * sc1 + sh1;
        float v2 = acc[nt][2] * sc0 + sh0;
        float v3 = acc[nt][3] * sc1 + sh1;
        v0 = v0 > 0.f ? v0 : expm1f(v0);
        v1 = v1 > 0.f ? v1 : expm1f(v1);
        v2 = v2 > 0.f ? v2 : expm1f(v2);
        v3 = v3 > 0.f ? v3 : expm1f(v3);
        *(float2*)(g_hbn + (size_t)r1 * HD + h * HID + n) = make_float2(v0, v1);
        *(float2*)(g_hbn + (size_t)r2 * HD + h * HID + n) = make_float2(v2, v3);
    }
}

// ---------------- a2 folds: warp per row of hbn ----------------
__global__ void a2_kernel() {
    int gw = (blockIdx.x * blockDim.x + threadIdx.x) >> 5;
    int lane = threadIdx.x & 31;
    if (gw >= N2) return;
    const float* row = g_hbn + (size_t)gw * HD + lane * 8;
    float4 r0 = *(const float4*)(row);
    float4 r1 = *(const float4*)(row + 4);
    float rv[8] = {r0.x, r0.y, r0.z, r0.w, r1.x, r1.y, r1.z, r1.w};
    float s = 0.f, d = 0.f;
#pragma unroll
    for (int i = 0; i < 8; i++) {
        int k = lane * 8 + i;
        s += rv[i] * g_v2s[k];
        d += rv[i] * g_v2d[k];
    }
#pragma unroll
    for (int off = 16; off > 0; off >>= 1) {
        s += __shfl_down_sync(0xffffffffu, s, off);
        d += __shfl_down_sync(0xffffffffu, d, off);
    }
    if (lane == 0) {
        g_as2[gw] = s;
        if (gw < N3) g_ad2[gw] = d;
    }
}

// ---------------- GEMM-L2 (mma.sync): h2 = hbn @ W2s ----------------
// grid N2/128, 256 threads. M=128, N=64, K=256 in 2 chunks of 128.
#define L2_SMEM (BF16_ELEMS * 2)
__global__ __launch_bounds__(256) void gemm_l2_mma(const float* __restrict__ W2s) {
    extern __shared__ __nv_bfloat16 smb[];
    unsigned short* sm = (unsigned short*)smb;
    int tid = threadIdx.x;
    int row0 = blockIdx.x * 128;
    int wid = tid >> 5, lane = tid & 31;
    int gr = lane >> 2, tg = lane & 3;
    int r0 = wid * 16;
    float acc[8][4];
#pragma unroll
    for (int nt = 0; nt < 8; nt++)
#pragma unroll
        for (int j = 0; j < 4; j++) acc[nt][j] = 0.f;

    for (int kb = 0; kb < HD; kb += 128) {
        if (kb) __syncthreads();
        for (int i = tid; i < 128 * 32; i += 256) {
            int row = i >> 5, k = (i & 31) * 4;
            float4 v = *(const float4*)(g_hbn + (size_t)(row0 + row) * HD + kb + k);
            unsigned short hi[4], lo[4];
            split_bf16(v.x, hi[0], lo[0]);
            split_bf16(v.y, hi[1], lo[1]);
            split_bf16(v.z, hi[2], lo[2]);
            split_bf16(v.w, hi[3], lo[3]);
            int o = row * SA + k;
            *(uint2*)(sm + AH_OFF + o) = make_uint2(pack2(hi[0], hi[1]), pack2(hi[2], hi[3]));
            *(uint2*)(sm + AL_OFF + o) = make_uint2(pack2(lo[0], lo[1]), pack2(lo[2], lo[3]));
        }
        for (int i = tid; i < 64 * 128; i += 256) {
            int n = i & 63, k = i >> 6;
            float v = W2s[(kb + k) * OUTD + n];
            unsigned short hi, lo;
            split_bf16(v, hi, lo);
            sm[BH_OFF + n * SA + k] = hi;
            sm[BL_OFF + n * SA + k] = lo;
        }
        __syncthreads();

#pragma unroll
        for (int ks = 0; ks < 8; ks++) {
            int k0 = ks * 16;
            int abase = (r0 + gr) * SA + k0 + tg * 2;
            uint32_t ah0 = *(const uint32_t*)(sm + AH_OFF + abase);
            uint32_t ah1 = *(const uint32_t*)(sm + AH_OFF + abase + 8 * SA);
            uint32_t ah2 = *(const uint32_t*)(sm + AH_OFF + abase + 8);
            uint32_t ah3 = *(const uint32_t*)(sm + AH_OFF + abase + 8 * SA + 8);
            uint32_t al0 = *(const uint32_t*)(sm + AL_OFF + abase);
            uint32_t al1 = *(const uint32_t*)(sm + AL_OFF + abase + 8 * SA);
            uint32_t al2 = *(const uint32_t*)(sm + AL_OFF + abase + 8);
            uint32_t al3 = *(const uint32_t*)(sm + AL_OFF + abase + 8 * SA + 8);
#pragma unroll
            for (int nt = 0; nt < 8; nt++) {
                int bbase = (nt * 8 + gr) * SA + k0 + tg * 2;
                uint32_t bh0 = *(const uint32_t*)(sm + BH_OFF + bbase);
                uint32_t bh1 = *(const uint32_t*)(sm + BH_OFF + bbase + 8);
                uint32_t bl0 = *(const uint32_t*)(sm + BL_OFF + bbase);
                uint32_t bl1 = *(const uint32_t*)(sm + BL_OFF + bbase + 8);
                mma16816(acc[nt], ah0, ah1, ah2, ah3, bh0, bh1);
                mma16816(acc[nt], ah0, ah1, ah2, ah3, bl0, bl1);
                mma16816(acc[nt], al0, al1, al2, al3, bh0, bh1);
            }
        }
    }

    int r1 = row0 + r0 + gr;
    int r2 = r1 + 8;
#pragma unroll
    for (int nt = 0; nt < 8; nt++) {
        int n = nt * 8 + tg * 2;
        *(float2*)(g_h2 + (size_t)r1 * OUTD + n) = make_float2(acc[nt][0], acc[nt][1]);
        *(float2*)(g_h2 + (size_t)r2 * OUTD + n) = make_float2(acc[nt][2], acc[nt][3]);
    }
}

// ---------------- layer2 alphas ----------------
__global__ void alpha2_kernel() {
    int d = (blockIdx.x * blockDim.x + threadIdx.x) >> 5;
    int lane = threadIdx.x & 31;
    if (d >= N3) return;
    int beg = g_off2[d], end = g_off2[d + 1];
    if (beg == end) return;
    float ad = g_ad2[d];
    float den = 0.f;
    for (int e = beg + lane; e < end; e += 32) {
        int s = g_srcs2[e];
        float ee = g_as2[s] + ad;
        ee = ee > 0.f ? ee : NEG_SLOPE * ee;
        float p = expf(ee);
        g_alpha2[e] = p;
        den += p;
    }
#pragma unroll
    for (int off = 16; off > 0; off >>= 1) den += __shfl_xor_sync(0xffffffffu, den, off);
    float rd = 1.f / fmaxf(den, 1e-16f);
    for (int e = beg + lane; e < end; e += 32) g_alpha2[e] *= rd;
}

// ---------------- layer2 aggregation into d_out ----------------
__global__ void agg2_kernel(float* __restrict__ out, const float* __restrict__ b2) {
    int d = (blockIdx.x * blockDim.x + threadIdx.x) >> 5;
    int lane = threadIdx.x & 31;
    if (d >= N3) return;
    int beg = g_off2[d], end = g_off2[d + 1];
    float ax = 0.f, ay = 0.f;
    for (int e = beg; e < end; e++) {
        int s = g_srcs2[e];
        float a = g_alpha2[e];
        float2 v = *(const float2*)(g_h2 + (size_t)s * OUTD + lane * 2);
        ax += a * v.x;
        ay += a * v.y;
    }
    out[(size_t)d * OUTD + lane * 2]     = ax + b2[lane * 2];
    out[(size_t)d * OUTD + lane * 2 + 1] = ay + b2[lane * 2 + 1];
}

// ---------------- launch ----------------
extern "C" void kernel_launch(void* const* d_in, const int* in_sizes, int n_in,
                              void* d_out, int out_size) {
    const float* x        = (const float*)d_in[0];
    const float* W1_src   = (const float*)d_in[1];
    const float* W1_dst   = (const float*)d_in[2];
    const float* att1_src = (const float*)d_in[3];
    const float* att1_dst = (const float*)d_in[4];
    const float* b1       = (const float*)d_in[5];
    const float* gamma    = (const float*)d_in[6];
    const float* beta     = (const float*)d_in[7];
    const float* run_mean = (const float*)d_in[8];
    const float* run_var  = (const float*)d_in[9];
    const float* W2_src   = (const float*)d_in[10];
    const float* W2_dst   = (const float*)d_in[11];
    const float* att2_src = (const float*)d_in[12];
    const float* att2_dst = (const float*)d_in[13];
    const float* b2       = (const float*)d_in[14];
    const int*   src1     = (const int*)d_in[15];
    const int*   dst1     = (const int*)d_in[16];
    const int*   src2     = (const int*)d_in[17];
    const int*   dst2     = (const int*)d_in[18];
    float* out = (float*)d_out;

    cudaFuncSetAttribute(gemm_l1_mma, cudaFuncAttributeMaxDynamicSharedMemorySize, L1_SMEM);
    cudaFuncSetAttribute(gemm_l2_mma, cudaFuncAttributeMaxDynamicSharedMemorySize, L2_SMEM);

    void* tmp;
    cudaGetSymbolAddress(&tmp, g_cur1);  int* d_cur1 = (int*)tmp;
    cudaGetSymbolAddress(&tmp, g_cur2);  int* d_cur2 = (int*)tmp;
    cudaGetSymbolAddress(&tmp, g_off1);  int* d_off1 = (int*)tmp;
    cudaGetSymbolAddress(&tmp, g_srcs1); int* d_srcs1 = (int*)tmp;
    cudaGetSymbolAddress(&tmp, g_off2);  int* d_off2 = (int*)tmp;
    cudaGetSymbolAddress(&tmp, g_srcs2); int* d_srcs2 = (int*)tmp;
    cudaGetSymbolAddress(&tmp, g_bsum);  int* d_bsum = (int*)tmp;

    cudaMemsetAsync(d_cur1, 0, N2 * sizeof(int), 0);
    cudaMemsetAsync(d_cur2, 0, N3 * sizeof(int), 0);

    fold_kernel<<<1, 512>>>(W1_src, att1_src, W1_dst, att1_dst, W2_src, W2_dst,
                            att2_src, att2_dst, b1, gamma, beta, run_mean, run_var);

    asrc1_kernel<<<N1 * 32 / 256, 256>>>(x);

    deg_kernel<<<E1 / 256, 256>>>(dst1, d_cur1, E1);
    scan_local<<<N2 / 4096, 1024>>>(d_cur1, d_off1, d_bsum);
    scan_bsum<<<1, 32>>>(d_bsum, d_off1, N2 / 4096, N2);
    scan_add<<<N2 / 1024, 1024>>>(d_off1, d_cur1, d_bsum);
    fill_kernel<<<E1 / 256, 256>>>(src1, dst1, d_cur1, d_srcs1, E1);

    alpha1_kernel<<<N2 / 8, 256>>>();
    agg1_kernel<<<N2 / 8, 256>>>(x);

    gemm_l1_mma<<<dim3(N2 / 128, HEADS), 256, L1_SMEM>>>(W1_src);
    a2_kernel<<<N2 / 8, 256>>>();

    deg_kernel<<<E2 / 256, 256>>>(dst2, d_cur2, E2);
    scan_local<<<N3 / 4096, 1024>>>(d_cur2, d_off2, d_bsum);
    scan_bsum<<<1, 32>>>(d_bsum, d_off2, N3 / 4096, N3);
    scan_add<<<N3 / 1024, 1024>>>(d_off2, d_cur2, d_bsum);
    fill_kernel<<<E2 / 256, 256>>>(src2, dst2, d_cur2, d_srcs2, E2);

    gemm_l2_mma<<<N2 / 128, 256, L2_SMEM>>>(W2_src);

    alpha2_kernel<<<N3 / 8, 256>>>();
    agg2_kernel<<<N3 / 8, 256>>>(out, b2);
}

// round 9
// speedup vs baseline: 1.7856x; 1.0738x over previous
#include <cuda_runtime.h>
#include <cuda_bf16.h>
#include <cstdint>

#define N1 262144
#define N2 65536
#define N3 16384
#define E1 524288
#define E2 262144
#define HD 256
#define HID 64
#define HEADS 4
#define OUTD 64
#define IND 128
#define NEG_SLOPE 0.2f

// ---------------- device scratch ----------------
__device__ float g_as1[(size_t)N1 * HEADS];
__device__ float g_ad1[(size_t)N2 * HEADS];
__device__ int   g_off1[N2 + 1];
__device__ int   g_cur1[N2];
__device__ int   g_srcs1[E1];
__device__ float g_alpha1[(size_t)E1 * HEADS];
__device__ float g_xagg[(size_t)N2 * HEADS * IND];
__device__ float g_hbn[(size_t)N2 * HD];
__device__ float g_h2[(size_t)N2 * OUTD];
__device__ float g_as2[N2];
__device__ float g_ad2[N3];
__device__ int   g_off2[N3 + 1];
__device__ int   g_cur2[N3];
__device__ int   g_srcs2[E2];
__device__ float g_alpha2[E2];
__device__ int   g_bsum[64];

__device__ float g_v1s[IND * HEADS];
__device__ float g_v1d[IND * HEADS];
__device__ float g_v2s[HD];
__device__ float g_v2d[HD];
__device__ float g_bnscale[HD];
__device__ float g_bnshift[HD];

// ---------------- mma.sync helper ----------------
__device__ __forceinline__ void mma16816(float* d, uint32_t a0, uint32_t a1, uint32_t a2,
                                         uint32_t a3, uint32_t b0, uint32_t b1) {
    asm volatile(
        "mma.sync.aligned.m16n8k16.row.col.f32.bf16.bf16.f32 "
        "{%0,%1,%2,%3}, {%4,%5,%6,%7}, {%8,%9}, {%0,%1,%2,%3};"
        : "+f"(d[0]), "+f"(d[1]), "+f"(d[2]), "+f"(d[3])
        : "r"(a0), "r"(a1), "r"(a2), "r"(a3), "r"(b0), "r"(b1));
}

__device__ __forceinline__ void split_bf16(float v, unsigned short& hi, unsigned short& lo) {
    __nv_bfloat16 h = __float2bfloat16_rn(v);
    float r = v - __bfloat162float(h);
    __nv_bfloat16 l = __float2bfloat16_rn(r);
    hi = __bfloat16_as_ushort(h);
    lo = __bfloat16_as_ushort(l);
}
__device__ __forceinline__ uint32_t pack2(unsigned short a, unsigned short b) {
    return (uint32_t)a | ((uint32_t)b << 16);
}

// ---------------- zero scratch (replaces 4 memsets) ----------------
__global__ void zero_kernel() {
    int i = blockIdx.x * 256 + threadIdx.x;
    if (i < N2) {
        g_cur1[i] = 0;
        g_as2[i] = 0.f;
    }
    if (i < N3) {
        g_cur2[i] = 0;
        g_ad2[i] = 0.f;
    }
}

// ---------------- fold ----------------
__global__ void fold_kernel(const float* __restrict__ W1s, const float* __restrict__ a1s,
                            const float* __restrict__ W1d, const float* __restrict__ a1d,
                            const float* __restrict__ W2s, const float* __restrict__ W2d,
                            const float* __restrict__ a2s, const float* __restrict__ a2d,
                            const float* __restrict__ b1, const float* __restrict__ gamma,
                            const float* __restrict__ beta, const float* __restrict__ mean,
                            const float* __restrict__ var) {
    int t = threadIdx.x;  // 512
    {
        int k = t >> 2, h = t & 3;
        float s1 = 0.f, d1 = 0.f;
        for (int c = 0; c < HID; c++) {
            s1 += W1s[k * HD + h * HID + c] * a1s[h * HID + c];
            d1 += W1d[k * HD + h * HID + c] * a1d[h * HID + c];
        }
        g_v1s[t] = s1;
        g_v1d[t] = d1;
    }
    if (t < HD) {
        float s2 = 0.f, d2 = 0.f;
        for (int c = 0; c < OUTD; c++) {
            s2 += W2s[t * OUTD + c] * a2s[c];
            d2 += W2d[t * OUTD + c] * a2d[c];
        }
        g_v2s[t] = s2;
        g_v2d[t] = d2;
        float sc = gamma[t] * rsqrtf(var[t] + 1e-5f);
        g_bnscale[t] = sc;
        g_bnshift[t] = beta[t] + (b1[t] - mean[t]) * sc;
    }
}

// ---------------- a_src1/a_dst1 ----------------
__global__ __launch_bounds__(256) void asrc1_kernel(const float* __restrict__ x) {
    __shared__ float sv1s[IND * HEADS], sv1d[IND * HEADS];
    int tid = threadIdx.x;
    for (int i = tid; i < IND * HEADS; i += 256) {
        sv1s[i] = g_v1s[i];
        sv1d[i] = g_v1d[i];
    }
    __syncthreads();
    int gw = (blockIdx.x * 256 + tid) >> 5;
    int lane = tid & 31;
    if (gw >= N1) return;
    float4 xv = *(const float4*)(x + (size_t)gw * IND + lane * 4);
    float xr[4] = {xv.x, xv.y, xv.z, xv.w};
    bool need_d = gw < N2;
    float s[4] = {0, 0, 0, 0}, dd[4] = {0, 0, 0, 0};
#pragma unroll
    for (int i = 0; i < 4; i++) {
        int k = lane * 4 + i;
#pragma unroll
        for (int h = 0; h < 4; h++) {
            s[h] += xr[i] * sv1s[k * HEADS + h];
            dd[h] += xr[i] * sv1d[k * HEADS + h];
        }
    }
#pragma unroll
    for (int off = 16; off > 0; off >>= 1)
#pragma unroll
        for (int h = 0; h < 4; h++) {
            s[h] += __shfl_down_sync(0xffffffffu, s[h], off);
            dd[h] += __shfl_down_sync(0xffffffffu, dd[h], off);
        }
    if (lane == 0) {
        *(float4*)(g_as1 + (size_t)gw * HEADS) = make_float4(s[0], s[1], s[2], s[3]);
        if (need_d)
            *(float4*)(g_ad1 + (size_t)gw * HEADS) = make_float4(dd[0], dd[1], dd[2], dd[3]);
    }
}

// ---------------- unified CSR build ----------------
__global__ void deg_all(const int* __restrict__ dst1, const int* __restrict__ dst2) {
    int i = blockIdx.x * 256 + threadIdx.x;
    if (i < E1) atomicAdd(&g_cur1[dst1[i]], 1);
    else atomicAdd(&g_cur2[dst2[i - E1]], 1);
}

__global__ __launch_bounds__(1024) void scan_local_all() {
    __shared__ int sm[1024];
    int b = blockIdx.x, t = threadIdx.x;
    const int* cnt;
    int* off;
    int* bs;
    int lb;
    if (b < 16) { cnt = g_cur1; off = g_off1; bs = g_bsum; lb = b; }
    else        { cnt = g_cur2; off = g_off2; bs = g_bsum + 32; lb = b - 16; }
    int base = lb * 4096 + t * 4;
    int4 v = *(const int4*)(cnt + base);
    int s = v.x + v.y + v.z + v.w;
    sm[t] = s;
    __syncthreads();
    for (int d = 1; d < 1024; d <<= 1) {
        int u = (t >= d) ? sm[t - d] : 0;
        __syncthreads();
        sm[t] += u;
        __syncthreads();
    }
    int excl = sm[t] - s;
    int4 o;
    o.x = excl;
    o.y = excl + v.x;
    o.z = o.y + v.y;
    o.w = o.z + v.z;
    *(int4*)(off + base) = o;
    if (t == 1023) bs[lb] = sm[1023];
}

__global__ void scan_bsum_all() {
    int w = threadIdx.x >> 5, t = threadIdx.x & 31;
    int* bs = g_bsum + w * 32;
    int nb = (w == 0) ? 16 : 4;
    int orig = (t < nb) ? bs[t] : 0;
    int v = orig;
    for (int d = 1; d < 32; d <<= 1) {
        int u = __shfl_up_sync(0xffffffffu, v, d);
        if (t >= d) v += u;
    }
    if (t < nb) bs[t] = v - orig;
    if (t == 31) {
        if (w == 0) g_off1[N2] = v;
        else g_off2[N3] = v;
    }
}

__global__ __launch_bounds__(1024) void scan_add_all() {
    int b = blockIdx.x, t = threadIdx.x;
    if (b < 64) {
        int i = b * 1024 + t;
        int v = g_off1[i] + g_bsum[i >> 12];
        g_off1[i] = v;
        g_cur1[i] = v;
    } else {
        int i = (b - 64) * 1024 + t;
        int v = g_off2[i] + g_bsum[32 + (i >> 12)];
        g_off2[i] = v;
        g_cur2[i] = v;
    }
}

__global__ void fill_all(const int* __restrict__ src1, const int* __restrict__ dst1,
                         const int* __restrict__ src2, const int* __restrict__ dst2) {
    int i = blockIdx.x * 256 + threadIdx.x;
    if (i < E1) {
        int pos = atomicAdd(&g_cur1[dst1[i]], 1);
        g_srcs1[pos] = src1[i];
    } else {
        int j = i - E1;
        int pos = atomicAdd(&g_cur2[dst2[j]], 1);
        g_srcs2[pos] = src2[j];
    }
}

// ---------------- layer1 fused softmax + aggregation: warp per dst ----------------
__global__ __launch_bounds__(256) void agg1f_kernel(const float* __restrict__ x) {
    int d = (blockIdx.x * blockDim.x + threadIdx.x) >> 5;
    int lane = threadIdx.x & 31;
    if (d >= N2) return;
    int beg = g_off1[d], end = g_off1[d + 1];
    float4 adv = *(const float4*)(g_ad1 + (size_t)d * HEADS);
    float ad[4] = {adv.x, adv.y, adv.z, adv.w};
    float den[4] = {0, 0, 0, 0};
    for (int e = beg + lane; e < end; e += 32) {
        int s = g_srcs1[e];
        float4 asv = *(const float4*)(g_as1 + (size_t)s * HEADS);
        float as[4] = {asv.x, asv.y, asv.z, asv.w};
        float p[4];
#pragma unroll
        for (int h = 0; h < 4; h++) {
            float ee = as[h] + ad[h];
            ee = ee > 0.f ? ee : NEG_SLOPE * ee;
            p[h] = expf(ee);
            den[h] += p[h];
        }
        *(float4*)(g_alpha1 + (size_t)e * HEADS) = make_float4(p[0], p[1], p[2], p[3]);
    }
#pragma unroll
    for (int off = 16; off > 0; off >>= 1)
#pragma unroll
        for (int h = 0; h < 4; h++) den[h] += __shfl_xor_sync(0xffffffffu, den[h], off);
    float rd[4];
#pragma unroll
    for (int h = 0; h < 4; h++) rd[h] = 1.f / fmaxf(den[h], 1e-16f);
    __syncwarp();
    __threadfence_block();   // make pass-1 alpha writes visible to all lanes
    float acc[4][4];
#pragma unroll
    for (int h = 0; h < 4; h++)
#pragma unroll
        for (int j = 0; j < 4; j++) acc[h][j] = 0.f;
    for (int e = beg; e < end; e++) {
        int s = g_srcs1[e];
        float4 al = *(const float4*)(g_alpha1 + (size_t)e * HEADS);
        float4 xv = *(const float4*)(x + (size_t)s * IND + lane * 4);
        float a[4] = {al.x * rd[0], al.y * rd[1], al.z * rd[2], al.w * rd[3]};
        float xr[4] = {xv.x, xv.y, xv.z, xv.w};
#pragma unroll
        for (int h = 0; h < 4; h++)
#pragma unroll
            for (int j = 0; j < 4; j++) acc[h][j] += a[h] * xr[j];
    }
#pragma unroll
    for (int h = 0; h < 4; h++)
        *(float4*)(g_xagg + ((size_t)d * HEADS + h) * IND + lane * 4) =
            make_float4(acc[h][0], acc[h][1], acc[h][2], acc[h][3]);
}

// ---------------- GEMM-L1 (mma.sync) + BN/ELU + a2 folds in epilogue ----------------
#define SA 132
#define AH_OFF 0
#define AL_OFF (128 * SA)
#define BH_OFF (2 * 128 * SA)
#define BL_OFF (2 * 128 * SA + 64 * SA)
#define BF16_ELEMS (2 * 128 * SA + 2 * 64 * SA)
#define L1_SMEM (BF16_ELEMS * 2 + 256 * 4)
__global__ __launch_bounds__(256) void gemm_l1_mma(const float* __restrict__ W1s) {
    extern __shared__ __nv_bfloat16 smb[];
    unsigned short* sm = (unsigned short*)smb;
    float* cons = (float*)(sm + BF16_ELEMS);  // sc[64] sh[64] v2s[64] v2d[64]
    int tid = threadIdx.x;
    int h = blockIdx.y;
    int row0 = blockIdx.x * 128;

    if (tid < 64) {
        int col = h * HID + tid;
        cons[tid]       = g_bnscale[col];
        cons[64 + tid]  = g_bnshift[col];
        cons[128 + tid] = g_v2s[col];
        cons[192 + tid] = g_v2d[col];
    }
    for (int i = tid; i < 128 * 32; i += 256) {
        int row = i >> 5, k = (i & 31) * 4;
        float4 v = *(const float4*)(g_xagg + ((size_t)(row0 + row) * HEADS + h) * IND + k);
        unsigned short hi[4], lo[4];
        split_bf16(v.x, hi[0], lo[0]);
        split_bf16(v.y, hi[1], lo[1]);
        split_bf16(v.z, hi[2], lo[2]);
        split_bf16(v.w, hi[3], lo[3]);
        int o = row * SA + k;
        *(uint2*)(sm + AH_OFF + o) = make_uint2(pack2(hi[0], hi[1]), pack2(hi[2], hi[3]));
        *(uint2*)(sm + AL_OFF + o) = make_uint2(pack2(lo[0], lo[1]), pack2(lo[2], lo[3]));
    }
    for (int i = tid; i < 64 * 128; i += 256) {
        int n = i & 63, k = i >> 6;
        float v = W1s[k * HD + h * HID + n];
        unsigned short hi, lo;
        split_bf16(v, hi, lo);
        sm[BH_OFF + n * SA + k] = hi;
        sm[BL_OFF + n * SA + k] = lo;
    }
    __syncthreads();

    int wid = tid >> 5, lane = tid & 31;
    int gr = lane >> 2, tg = lane & 3;
    int r0 = wid * 16;
    float acc[8][4];
#pragma unroll
    for (int nt = 0; nt < 8; nt++)
#pragma unroll
        for (int j = 0; j < 4; j++) acc[nt][j] = 0.f;

#pragma unroll
    for (int ks = 0; ks < 8; ks++) {
        int k0 = ks * 16;
        int abase = (r0 + gr) * SA + k0 + tg * 2;
        uint32_t ah0 = *(const uint32_t*)(sm + AH_OFF + abase);
        uint32_t ah1 = *(const uint32_t*)(sm + AH_OFF + abase + 8 * SA);
        uint32_t ah2 = *(const uint32_t*)(sm + AH_OFF + abase + 8);
        uint32_t ah3 = *(const uint32_t*)(sm + AH_OFF + abase + 8 * SA + 8);
        uint32_t al0 = *(const uint32_t*)(sm + AL_OFF + abase);
        uint32_t al1 = *(const uint32_t*)(sm + AL_OFF + abase + 8 * SA);
        uint32_t al2 = *(const uint32_t*)(sm + AL_OFF + abase + 8);
        uint32_t al3 = *(const uint32_t*)(sm + AL_OFF + abase + 8 * SA + 8);
#pragma unroll
        for (int nt = 0; nt < 8; nt++) {
            int bbase = (nt * 8 + gr) * SA + k0 + tg * 2;
            uint32_t bh0 = *(const uint32_t*)(sm + BH_OFF + bbase);
            uint32_t bh1 = *(const uint32_t*)(sm + BH_OFF + bbase + 8);
            uint32_t bl0 = *(const uint32_t*)(sm + BL_OFF + bbase);
            uint32_t bl1 = *(const uint32_t*)(sm + BL_OFF + bbase + 8);
            mma16816(acc[nt], ah0, ah1, ah2, ah3, bh0, bh1);
            mma16816(acc[nt], ah0, ah1, ah2, ah3, bl0, bl1);
            mma16816(acc[nt], al0, al1, al2, al3, bh0, bh1);
        }
    }

    int r1 = row0 + r0 + gr;
    int r2 = r1 + 8;
    float ps1 = 0.f, pd1 = 0.f, ps2 = 0.f, pd2 = 0.f;
#pragma unroll
    for (int nt = 0; nt < 8; nt++) {
        int n = nt * 8 + tg * 2;
        float sc0 = cons[n], sc1 = cons[n + 1], sh0 = cons[64 + n], sh1 = cons[64 + n + 1];
        float vs0 = cons[128 + n], vs1 = cons[128 + n + 1];
        float vd0 = cons[192 + n], vd1 = cons[192 + n + 1];
        float v0 = acc[nt][0] * sc0 + sh0;
        float v1 = acc[nt][1] * sc1 + sh1;
        float v2 = acc[nt][2] * sc0 + sh0;
        float v3 = acc[nt][3] * sc1 + sh1;
        v0 = v0 > 0.f ? v0 : expm1f(v0);
        v1 = v1 > 0.f ? v1 : expm1f(v1);
        v2 = v2 > 0.f ? v2 : expm1f(v2);
        v3 = v3 > 0.f ? v3 : expm1f(v3);
        *(float2*)(g_hbn + (size_t)r1 * HD + h * HID + n) = make_float2(v0, v1);
        *(float2*)(g_hbn + (size_t)r2 * HD + h * HID + n) = make_float2(v2, v3);
        ps1 += v0 * vs0 + v1 * vs1;
        ps2 += v2 * vs0 + v3 * vs1;
        pd1 += v0 * vd0 + v1 * vd1;
        pd2 += v2 * vd0 + v3 * vd1;
    }
#pragma unroll
    for (int off = 2; off > 0; off >>= 1) {
        ps1 += __shfl_down_sync(0xffffffffu, ps1, off, 4);
        ps2 += __shfl_down_sync(0xffffffffu, ps2, off, 4);
        pd1 += __shfl_down_sync(0xffffffffu, pd1, off, 4);
        pd2 += __shfl_down_sync(0xffffffffu, pd2, off, 4);
    }
    if (tg == 0) {
        atomicAdd(&g_as2[r1], ps1);
        atomicAdd(&g_as2[r2], ps2);
        if (r1 < N3) atomicAdd(&g_ad2[r1], pd1);
        if (r2 < N3) atomicAdd(&g_ad2[r2], pd2);
    }
}

// ---------------- GEMM-L2 (mma.sync): h2 = hbn @ W2s ----------------
#define L2_SMEM (BF16_ELEMS * 2)
__global__ __launch_bounds__(256) void gemm_l2_mma(const float* __restrict__ W2s) {
    extern __shared__ __nv_bfloat16 smb[];
    unsigned short* sm = (unsigned short*)smb;
    int tid = threadIdx.x;
    int row0 = blockIdx.x * 128;
    int wid = tid >> 5, lane = tid & 31;
    int gr = lane >> 2, tg = lane & 3;
    int r0 = wid * 16;
    float acc[8][4];
#pragma unroll
    for (int nt = 0; nt < 8; nt++)
#pragma unroll
        for (int j = 0; j < 4; j++) acc[nt][j] = 0.f;

    for (int kb = 0; kb < HD; kb += 128) {
        if (kb) __syncthreads();
        for (int i = tid; i < 128 * 32; i += 256) {
            int row = i >> 5, k = (i & 31) * 4;
            float4 v = *(const float4*)(g_hbn + (size_t)(row0 + row) * HD + kb + k);
            unsigned short hi[4], lo[4];
            split_bf16(v.x, hi[0], lo[0]);
            split_bf16(v.y, hi[1], lo[1]);
            split_bf16(v.z, hi[2], lo[2]);
            split_bf16(v.w, hi[3], lo[3]);
            int o = row * SA + k;
            *(uint2*)(sm + AH_OFF + o) = make_uint2(pack2(hi[0], hi[1]), pack2(hi[2], hi[3]));
            *(uint2*)(sm + AL_OFF + o) = make_uint2(pack2(lo[0], lo[1]), pack2(lo[2], lo[3]));
        }
        for (int i = tid; i < 64 * 128; i += 256) {
            int n = i & 63, k = i >> 6;
            float v = W2s[(kb + k) * OUTD + n];
            unsigned short hi, lo;
            split_bf16(v, hi, lo);
            sm[BH_OFF + n * SA + k] = hi;
            sm[BL_OFF + n * SA + k] = lo;
        }
        __syncthreads();

#pragma unroll
        for (int ks = 0; ks < 8; ks++) {
            int k0 = ks * 16;
            int abase = (r0 + gr) * SA + k0 + tg * 2;
            uint32_t ah0 = *(const uint32_t*)(sm + AH_OFF + abase);
            uint32_t ah1 = *(const uint32_t*)(sm + AH_OFF + abase + 8 * SA);
            uint32_t ah2 = *(const uint32_t*)(sm + AH_OFF + abase + 8);
            uint32_t ah3 = *(const uint32_t*)(sm + AH_OFF + abase + 8 * SA + 8);
            uint32_t al0 = *(const uint32_t*)(sm + AL_OFF + abase);
            uint32_t al1 = *(const uint32_t*)(sm + AL_OFF + abase + 8 * SA);
            uint32_t al2 = *(const uint32_t*)(sm + AL_OFF + abase + 8);
            uint32_t al3 = *(const uint32_t*)(sm + AL_OFF + abase + 8 * SA + 8);
#pragma unroll
            for (int nt = 0; nt < 8; nt++) {
                int bbase = (nt * 8 + gr) * SA + k0 + tg * 2;
                uint32_t bh0 = *(const uint32_t*)(sm + BH_OFF + bbase);
                uint32_t bh1 = *(const uint32_t*)(sm + BH_OFF + bbase + 8);
                uint32_t bl0 = *(const uint32_t*)(sm + BL_OFF + bbase);
                uint32_t bl1 = *(const uint32_t*)(sm + BL_OFF + bbase + 8);
                mma16816(acc[nt], ah0, ah1, ah2, ah3, bh0, bh1);
                mma16816(acc[nt], ah0, ah1, ah2, ah3, bl0, bl1);
                mma16816(acc[nt], al0, al1, al2, al3, bh0, bh1);
            }
        }
    }

    int r1 = row0 + r0 + gr;
    int r2 = r1 + 8;
#pragma unroll
    for (int nt = 0; nt < 8; nt++) {
        int n = nt * 8 + tg * 2;
        *(float2*)(g_h2 + (size_t)r1 * OUTD + n) = make_float2(acc[nt][0], acc[nt][1]);
        *(float2*)(g_h2 + (size_t)r2 * OUTD + n) = make_float2(acc[nt][2], acc[nt][3]);
    }
}

// ---------------- layer2 fused softmax + aggregation into d_out ----------------
__global__ __launch_bounds__(256) void agg2f_kernel(float* __restrict__ out,
                                                    const float* __restrict__ b2) {
    int d = (blockIdx.x * blockDim.x + threadIdx.x) >> 5;
    int lane = threadIdx.x & 31;
    if (d >= N3) return;
    int beg = g_off2[d], end = g_off2[d + 1];
    float ad = g_ad2[d];
    float den = 0.f;
    for (int e = beg + lane; e < end; e += 32) {
        int s = g_srcs2[e];
        float ee = g_as2[s] + ad;
        ee = ee > 0.f ? ee : NEG_SLOPE * ee;
        float p = expf(ee);
        g_alpha2[e] = p;
        den += p;
    }
#pragma unroll
    for (int off = 16; off > 0; off >>= 1) den += __shfl_xor_sync(0xffffffffu, den, off);
    float rd = 1.f / fmaxf(den, 1e-16f);
    __syncwarp();
    __threadfence_block();
    float ax = 0.f, ay = 0.f;
    for (int e = beg; e < end; e++) {
        int s = g_srcs2[e];
        float a = g_alpha2[e] * rd;
        float2 v = *(const float2*)(g_h2 + (size_t)s * OUTD + lane * 2);
        ax += a * v.x;
        ay += a * v.y;
    }
    out[(size_t)d * OUTD + lane * 2]     = ax + b2[lane * 2];
    out[(size_t)d * OUTD + lane * 2 + 1] = ay + b2[lane * 2 + 1];
}

// ---------------- launch ----------------
extern "C" void kernel_launch(void* const* d_in, const int* in_sizes, int n_in,
                              void* d_out, int out_size) {
    const float* x        = (const float*)d_in[0];
    const float* W1_src   = (const float*)d_in[1];
    const float* W1_dst   = (const float*)d_in[2];
    const float* att1_src = (const float*)d_in[3];
    const float* att1_dst = (const float*)d_in[4];
    const float* b1       = (const float*)d_in[5];
    const float* gamma    = (const float*)d_in[6];
    const float* beta     = (const float*)d_in[7];
    const float* run_mean = (const float*)d_in[8];
    const float* run_var  = (const float*)d_in[9];
    const float* W2_src   = (const float*)d_in[10];
    const float* W2_dst   = (const float*)d_in[11];
    const float* att2_src = (const float*)d_in[12];
    const float* att2_dst = (const float*)d_in[13];
    const float* b2       = (const float*)d_in[14];
    const int*   src1     = (const int*)d_in[15];
    const int*   dst1     = (const int*)d_in[16];
    const int*   src2     = (const int*)d_in[17];
    const int*   dst2     = (const int*)d_in[18];
    float* out = (float*)d_out;

    cudaFuncSetAttribute(gemm_l1_mma, cudaFuncAttributeMaxDynamicSharedMemorySize, L1_SMEM);
    cudaFuncSetAttribute(gemm_l2_mma, cudaFuncAttributeMaxDynamicSharedMemorySize, L2_SMEM);

    zero_kernel<<<N2 / 256, 256>>>();
    fold_kernel<<<1, 512>>>(W1_src, att1_src, W1_dst, att1_dst, W2_src, W2_dst,
                            att2_src, att2_dst, b1, gamma, beta, run_mean, run_var);

    asrc1_kernel<<<N1 * 32 / 256, 256>>>(x);

    deg_all<<<(E1 + E2) / 256, 256>>>(dst1, dst2);
    scan_local_all<<<20, 1024>>>();
    scan_bsum_all<<<1, 64>>>();
    scan_add_all<<<80, 1024>>>();
    fill_all<<<(E1 + E2) / 256, 256>>>(src1, dst1, src2, dst2);

    agg1f_kernel<<<N2 / 8, 256>>>(x);

    gemm_l1_mma<<<dim3(N2 / 128, HEADS), 256, L1_SMEM>>>(W1_src);

    gemm_l2_mma<<<N2 / 128, 256, L2_SMEM>>>(W2_src);

    agg2f_kernel<<<N3 / 8, 256>>>(out, b2);
}